// round 15
// baseline (speedup 1.0000x reference)
#include <cuda_runtime.h>
#include <stdint.h>

// ============================================================================
// LoraSubnet: top-(1-k) threshold mask for two matrices.
// out[0:nA)  = mask_A, out[nA:nA+nB) = mask_B  (float32 0.0 / 1.0)
// Rank j = int(0.9 * n) lowest |values| (stable ties by flat index) -> 0, rest -> 1.
//
// Pipeline: sampled coarse histogram -> band select -> fused mask-write +
// in-band gather -> exact 2-level refinement on gathered -> scatter fixup.
// Exact and deterministic (all reductions are integer / order-invariant).
// ============================================================================

#define SPARSITY_K 0.1
#define BINS1 32768          // coarse bins: abs-bits >> 16
#define SHIFT1 16
#define FB 65536             // fine histogram bins (16-bit)
#define GCAP (1u << 21)      // gather capacity per matrix (2M entries)
#define TIECAP 16384
#define MARGIN_RANKS 350000.0

__device__ unsigned int       g_hist1[2][BINS1];
__device__ int                g_binLo[2];
__device__ int                g_binHi[2];
__device__ unsigned long long g_count_less[2];   // exact count of elems below band
__device__ unsigned int       g_gcount[2];       // gathered count
__device__ uint2              g_gather[2][GCAP]; // (abs_bits, flat_idx)
__device__ unsigned int       g_fhist1[2][FB];   // hist on bits>>16 of gathered
__device__ unsigned int       g_fhist2[2][FB];   // hist on bits&0xFFFF within bucket
__device__ unsigned int       g_bucket[2];
__device__ unsigned long long g_rank_before[2];  // # elems with bucket < g_bucket
__device__ unsigned int       g_tbits[2];        // exact threshold bit pattern
__device__ long long          g_z[2];            // # tied-at-threshold elems to zero
__device__ unsigned int       g_tie[2][TIECAP];
__device__ unsigned int       g_tiecnt[2];

__device__ __forceinline__ long long keep_j(long long n) {
    // mirrors python: int((1.0 - k) * n), double math, truncate
    return (long long)((1.0 - SPARSITY_K) * (double)n);
}

__device__ __forceinline__ unsigned int abs_bits(float x) {
    return __float_as_uint(x) & 0x7fffffffu;
}

// ---------------------------------------------------------------------------
__global__ void k_clear() {
    unsigned t = blockIdx.x * blockDim.x + threadIdx.x;
    unsigned T = gridDim.x * blockDim.x;
    unsigned* h1 = (unsigned*)g_hist1;
    for (unsigned i = t; i < 2u * BINS1; i += T) h1[i] = 0u;
    unsigned* f1 = (unsigned*)g_fhist1;
    unsigned* f2 = (unsigned*)g_fhist2;
    for (unsigned i = t; i < 2u * FB; i += T) { f1[i] = 0u; f2[i] = 0u; }
    if (t < 2u) { g_count_less[t] = 0ull; g_gcount[t] = 0u; g_tiecnt[t] = 0u; }
}

// ---------------------------------------------------------------------------
// Sample every 64th float4 (1/64 of the data) into the coarse histogram.
__global__ void k_sample(const float* __restrict__ A, const float* __restrict__ B,
                         int n4A, int n4B) {
    int m = blockIdx.y;
    const float4* src = (const float4*)(m ? B : A);
    long long n4 = m ? n4B : n4A;
    long long t = (long long)blockIdx.x * blockDim.x + threadIdx.x;
    long long T = (long long)gridDim.x * blockDim.x;
    for (long long s = t; s * 64 < n4; s += T) {
        float4 v = src[s * 64];
        atomicAdd(&g_hist1[m][abs_bits(v.x) >> SHIFT1], 1u);
        atomicAdd(&g_hist1[m][abs_bits(v.y) >> SHIFT1], 1u);
        atomicAdd(&g_hist1[m][abs_bits(v.z) >> SHIFT1], 1u);
        atomicAdd(&g_hist1[m][abs_bits(v.w) >> SHIFT1], 1u);
    }
}

// ---------------------------------------------------------------------------
// Find conservative coarse-bin band containing rank j (one block per matrix).
__global__ void __launch_bounds__(1024) k_band(long long nA, long long nB) {
    int m = blockIdx.x;
    long long n = m ? nB : nA;
    long long j = keep_j(n);
    const int W = BINS1 / 1024;  // 32 bins per thread
    __shared__ unsigned long long part[1024];
    int t = threadIdx.x;
    unsigned long long s = 0;
    for (int i = 0; i < W; i++) s += g_hist1[m][t * W + i];
    part[t] = s;
    __syncthreads();
    if (t == 0) {
        unsigned long long S = 0;
        for (int i = 0; i < 1024; i++) S += part[i];
        double scale = (S > 0) ? (double)S / (double)n : 0.0;
        double lo_t = ((double)j - MARGIN_RANKS) * scale; if (lo_t < 0.0) lo_t = 0.0;
        double hi_t = ((double)j + MARGIN_RANKS) * scale;
        unsigned long long cum = 0;
        int lo = BINS1 - 1, hi = BINS1 - 1;
        bool fl = false, fh = false;
        for (int i = 0; i < 1024 && !fh; i++) {
            unsigned long long nc = cum + part[i];
            if ((!fl && (double)nc >= lo_t) || (!fh && (double)nc >= hi_t)) {
                unsigned long long c2 = cum;
                for (int k = 0; k < W; k++) {
                    c2 += g_hist1[m][i * W + k];
                    if (!fl && (double)c2 >= lo_t) { lo = i * W + k; fl = true; }
                    if (!fh && (double)c2 >= hi_t) { hi = i * W + k; fh = true; break; }
                }
            }
            cum = nc;
        }
        if (!fl) lo = BINS1 - 1;
        if (!fh) hi = BINS1 - 1;
        if (hi < lo) hi = lo;
        g_binLo[m] = lo;
        g_binHi[m] = hi;
    }
}

// ---------------------------------------------------------------------------
// The single full pass: write mask (tentative 0 for band), count below-band,
// gather in-band (bits, idx) with block-aggregated atomics.
__global__ void __launch_bounds__(1024) k_mask(const float* __restrict__ A,
                                               const float* __restrict__ B,
                                               float* __restrict__ out,
                                               int nA_i, int nB_i, long long nA) {
    int m = blockIdx.y;
    const float* srcf = m ? B : A;
    float* outf = out + (m ? nA : 0);
    int n = m ? nB_i : nA_i;
    int n4 = n >> 2;
    const float4* src4 = (const float4*)srcf;
    float4* out4 = (float4*)outf;
    const int lo = g_binLo[m];
    const int hi = g_binHi[m];

    __shared__ unsigned int sCnt;
    __shared__ unsigned int sBase;

    int t = blockIdx.x * blockDim.x + threadIdx.x;
    int T = gridDim.x * blockDim.x;
    int iters = (n4 + T - 1) / T;
    unsigned long long lless = 0;

    for (int it = 0; it < iters; it++) {
        int i4 = t + it * T;
        bool valid = (i4 < n4);
        if (threadIdx.x == 0) sCnt = 0u;
        __syncthreads();

        float r[4];
        unsigned int lb[4];
        unsigned int li[4];
        int lcnt = 0;
        if (valid) {
            float4 v = src4[i4];
            float vv[4] = {v.x, v.y, v.z, v.w};
#pragma unroll
            for (int c = 0; c < 4; c++) {
                unsigned int b = abs_bits(vv[c]);
                int bin = (int)(b >> SHIFT1);
                if (bin < lo) { r[c] = 0.0f; lless++; }
                else if (bin > hi) { r[c] = 1.0f; }
                else {
                    r[c] = 0.0f;
                    lb[lcnt] = b;
                    li[lcnt] = (unsigned int)(i4 * 4 + c);
                    lcnt++;
                }
            }
        }
        unsigned int myoff = 0;
        if (lcnt) myoff = atomicAdd(&sCnt, (unsigned int)lcnt);
        __syncthreads();
        if (threadIdx.x == 0) sBase = sCnt ? atomicAdd(&g_gcount[m], sCnt) : 0u;
        __syncthreads();
        if (lcnt) {
            unsigned int base = sBase + myoff;
            for (int k = 0; k < lcnt; k++) {
                unsigned int p = base + (unsigned int)k;
                if (p < GCAP) g_gather[m][p] = make_uint2(lb[k], li[k]);
            }
        }
        if (valid) out4[i4] = make_float4(r[0], r[1], r[2], r[3]);
    }

    // scalar tail (n % 4)
    int rem = n - n4 * 4;
    if (blockIdx.x == 0 && (int)threadIdx.x < rem) {
        int idx = n4 * 4 + (int)threadIdx.x;
        unsigned int b = abs_bits(srcf[idx]);
        int bin = (int)(b >> SHIFT1);
        float r;
        if (bin < lo) { r = 0.0f; lless++; }
        else if (bin > hi) { r = 1.0f; }
        else {
            r = 0.0f;
            unsigned int p = atomicAdd(&g_gcount[m], 1u);
            if (p < GCAP) g_gather[m][p] = make_uint2(b, (unsigned int)idx);
        }
        outf[idx] = r;
    }

    // reduce below-band count: warp reduce, then one atomic per warp
#pragma unroll
    for (int off = 16; off > 0; off >>= 1)
        lless += __shfl_down_sync(0xffffffffu, lless, off);
    if ((threadIdx.x & 31) == 0 && lless)
        atomicAdd(&g_count_less[m], lless);
}

// ---------------------------------------------------------------------------
__global__ void k_fhist1() {
    int m = blockIdx.y;
    unsigned int cnt = g_gcount[m]; if (cnt > GCAP) cnt = GCAP;
    unsigned int t = blockIdx.x * blockDim.x + threadIdx.x;
    unsigned int T = gridDim.x * blockDim.x;
    for (unsigned int i = t; i < cnt; i += T)
        atomicAdd(&g_fhist1[m][g_gather[m][i].x >> 16], 1u);
}

__global__ void __launch_bounds__(1024) k_scan1(long long nA, long long nB) {
    int m = blockIdx.x;
    long long n = m ? nB : nA;
    long long j = keep_j(n);
    __shared__ unsigned long long part[1024];
    int t = threadIdx.x;
    unsigned long long s = 0;
    for (int i = 0; i < FB / 1024; i++) s += g_fhist1[m][t * (FB / 1024) + i];
    part[t] = s;
    __syncthreads();
    if (t == 0) {
        long long need = j + 1 - (long long)g_count_less[m];
        if (need < 1) need = 1;  // degenerate guard
        unsigned long long cum = 0;
        int bucket = FB - 1;
        for (int i = 0; i < 1024; i++) {
            if ((long long)(cum + part[i]) >= need) {
                for (int k = 0; k < FB / 1024; k++) {
                    unsigned int h = g_fhist1[m][i * (FB / 1024) + k];
                    if ((long long)(cum + h) >= need) { bucket = i * (FB / 1024) + k; break; }
                    cum += h;
                }
                break;
            }
            cum += part[i];
        }
        g_bucket[m] = (unsigned int)bucket;
        g_rank_before[m] = g_count_less[m] + cum;  // # elems strictly below bucket
    }
}

__global__ void k_fhist2() {
    int m = blockIdx.y;
    unsigned int cnt = g_gcount[m]; if (cnt > GCAP) cnt = GCAP;
    unsigned int bkt = g_bucket[m];
    unsigned int t = blockIdx.x * blockDim.x + threadIdx.x;
    unsigned int T = gridDim.x * blockDim.x;
    for (unsigned int i = t; i < cnt; i += T) {
        uint2 e = g_gather[m][i];
        if ((e.x >> 16) == bkt) atomicAdd(&g_fhist2[m][e.x & 0xffffu], 1u);
    }
}

__global__ void __launch_bounds__(1024) k_scan2(long long nA, long long nB) {
    int m = blockIdx.x;
    long long n = m ? nB : nA;
    long long j = keep_j(n);
    __shared__ unsigned long long part[1024];
    int t = threadIdx.x;
    unsigned long long s = 0;
    for (int i = 0; i < FB / 1024; i++) s += g_fhist2[m][t * (FB / 1024) + i];
    part[t] = s;
    __syncthreads();
    if (t == 0) {
        long long need = j + 1 - (long long)g_rank_before[m];
        if (need < 1) need = 1;
        unsigned long long cum = 0;
        int L = FB - 1;
        for (int i = 0; i < 1024; i++) {
            if ((long long)(cum + part[i]) >= need) {
                for (int k = 0; k < FB / 1024; k++) {
                    unsigned int h = g_fhist2[m][i * (FB / 1024) + k];
                    if ((long long)(cum + h) >= need) { L = i * (FB / 1024) + k; break; }
                    cum += h;
                }
                break;
            }
            cum += part[i];
        }
        g_tbits[m] = (g_bucket[m] << 16) | (unsigned int)L;
        long long cntLess = (long long)g_rank_before[m] + (long long)cum;
        g_z[m] = j - cntLess;  // first z tied elems (by flat idx) stay 0
    }
}

// ---------------------------------------------------------------------------
// Scatter 1s for gathered entries strictly above threshold; collect exact ties.
__global__ void k_scatter(float* __restrict__ out, long long nA) {
    int m = blockIdx.y;
    float* outf = out + (m ? nA : 0);
    unsigned int cnt = g_gcount[m]; if (cnt > GCAP) cnt = GCAP;
    unsigned int tb = g_tbits[m];
    long long z = g_z[m];
    unsigned int t = blockIdx.x * blockDim.x + threadIdx.x;
    unsigned int T = gridDim.x * blockDim.x;
    for (unsigned int i = t; i < cnt; i += T) {
        uint2 e = g_gather[m][i];
        if (e.x > tb) {
            outf[e.y] = 1.0f;
        } else if (e.x == tb) {
            if (z == 0) {
                outf[e.y] = 1.0f;
            } else {
                unsigned int p = atomicAdd(&g_tiecnt[m], 1u);
                if (p < TIECAP) g_tie[m][p] = e.y;
            }
        }
    }
}

// Among tied elements, the z smallest flat indices stay 0; the rest -> 1.
__global__ void k_ties(float* __restrict__ out, long long nA) {
    int m = blockIdx.x;
    float* outf = out + (m ? nA : 0);
    unsigned int mt = g_tiecnt[m]; if (mt > TIECAP) mt = TIECAP;
    long long z = g_z[m];
    for (unsigned int i = threadIdx.x; i < mt; i += blockDim.x) {
        unsigned int my = g_tie[m][i];
        long long c = 0;
        for (unsigned int u = 0; u < mt; u++) c += (g_tie[m][u] < my) ? 1 : 0;
        if (c >= z) outf[my] = 1.0f;
    }
}

// ---------------------------------------------------------------------------
extern "C" void kernel_launch(void* const* d_in, const int* in_sizes, int n_in,
                              void* d_out, int out_size) {
    const float* A = (const float*)d_in[0];
    const float* B = (const float*)d_in[1];
    float* out = (float*)d_out;
    long long nA = in_sizes[0];
    long long nB = (n_in > 1) ? in_sizes[1] : 0;
    int n4A = (int)(nA >> 2);
    int n4B = (int)(nB >> 2);

    k_clear<<<256, 256>>>();

    dim3 gs(256, 2);
    k_sample<<<gs, 256>>>(A, B, n4A, n4B);

    k_band<<<2, 1024>>>(nA, nB);

    dim3 gm(592, 2);
    k_mask<<<gm, 1024>>>(A, B, out, (int)nA, (int)nB, nA);

    dim3 gf(148, 2);
    k_fhist1<<<gf, 256>>>();
    k_scan1<<<2, 1024>>>(nA, nB);
    k_fhist2<<<gf, 256>>>();
    k_scan2<<<2, 1024>>>(nA, nB);
    k_scatter<<<gf, 256>>>(out, nA);
    k_ties<<<2, 256>>>(out, nA);
}

// round 16
// speedup vs baseline: 1.0036x; 1.0036x over previous
#include <cuda_runtime.h>
#include <stdint.h>

// ============================================================================
// LoraSubnet: top-(1-k) threshold mask for two matrices.
// out[0:nA)  = mask_A, out[nA:nA+nB) = mask_B  (float32 0.0 / 1.0)
// Rank j = int(0.9 * n) lowest |values| (stable ties by flat index) -> 0, rest -> 1.
//
// Pipeline: sampled coarse histogram -> band select -> fused mask-write +
// in-band gather -> exact 2-level refinement on gathered -> scatter fixup.
// Exact and deterministic (all reductions are integer / order-invariant).
// ============================================================================

#define SPARSITY_K 0.1
#define BINS1 32768          // coarse bins: abs-bits >> 16
#define SHIFT1 16
#define FB 65536             // fine histogram bins (16-bit)
#define GCAP (1u << 21)      // gather capacity per matrix (2M entries)
#define TIECAP 16384
#define MARGIN_RANKS 350000.0

__device__ unsigned int       g_hist1[2][BINS1];
__device__ int                g_binLo[2];
__device__ int                g_binHi[2];
__device__ unsigned long long g_count_less[2];   // exact count of elems below band
__device__ unsigned int       g_gcount[2];       // gathered count
__device__ uint2              g_gather[2][GCAP]; // (abs_bits, flat_idx)
__device__ unsigned int       g_fhist1[2][FB];   // hist on bits>>16 of gathered
__device__ unsigned int       g_fhist2[2][FB];   // hist on bits&0xFFFF within bucket
__device__ unsigned int       g_bucket[2];
__device__ unsigned long long g_rank_before[2];  // # elems with bucket < g_bucket
__device__ unsigned int       g_tbits[2];        // exact threshold bit pattern
__device__ long long          g_z[2];            // # tied-at-threshold elems to zero
__device__ unsigned int       g_tie[2][TIECAP];
__device__ unsigned int       g_tiecnt[2];

__device__ __forceinline__ long long keep_j(long long n) {
    // mirrors python: int((1.0 - k) * n), double math, truncate
    return (long long)((1.0 - SPARSITY_K) * (double)n);
}

__device__ __forceinline__ unsigned int abs_bits(float x) {
    return __float_as_uint(x) & 0x7fffffffu;
}

// ---------------------------------------------------------------------------
__global__ void k_clear() {
    unsigned t = blockIdx.x * blockDim.x + threadIdx.x;
    unsigned T = gridDim.x * blockDim.x;
    unsigned* h1 = (unsigned*)g_hist1;
    for (unsigned i = t; i < 2u * BINS1; i += T) h1[i] = 0u;
    unsigned* f1 = (unsigned*)g_fhist1;
    unsigned* f2 = (unsigned*)g_fhist2;
    for (unsigned i = t; i < 2u * FB; i += T) { f1[i] = 0u; f2[i] = 0u; }
    if (t < 2u) { g_count_less[t] = 0ull; g_gcount[t] = 0u; g_tiecnt[t] = 0u; }
}

// ---------------------------------------------------------------------------
// Sample every 64th float4 (1/64 of the data) into the coarse histogram.
__global__ void k_sample(const float* __restrict__ A, const float* __restrict__ B,
                         int n4A, int n4B) {
    int m = blockIdx.y;
    const float4* src = (const float4*)(m ? B : A);
    long long n4 = m ? n4B : n4A;
    long long t = (long long)blockIdx.x * blockDim.x + threadIdx.x;
    long long T = (long long)gridDim.x * blockDim.x;
    for (long long s = t; s * 64 < n4; s += T) {
        float4 v = src[s * 64];
        atomicAdd(&g_hist1[m][abs_bits(v.x) >> SHIFT1], 1u);
        atomicAdd(&g_hist1[m][abs_bits(v.y) >> SHIFT1], 1u);
        atomicAdd(&g_hist1[m][abs_bits(v.z) >> SHIFT1], 1u);
        atomicAdd(&g_hist1[m][abs_bits(v.w) >> SHIFT1], 1u);
    }
}

// ---------------------------------------------------------------------------
// Find conservative coarse-bin band containing rank j (one block per matrix).
__global__ void __launch_bounds__(1024) k_band(long long nA, long long nB) {
    int m = blockIdx.x;
    long long n = m ? nB : nA;
    long long j = keep_j(n);
    const int W = BINS1 / 1024;  // 32 bins per thread
    __shared__ unsigned long long part[1024];
    int t = threadIdx.x;
    unsigned long long s = 0;
    for (int i = 0; i < W; i++) s += g_hist1[m][t * W + i];
    part[t] = s;
    __syncthreads();
    if (t == 0) {
        unsigned long long S = 0;
        for (int i = 0; i < 1024; i++) S += part[i];
        double scale = (S > 0) ? (double)S / (double)n : 0.0;
        double lo_t = ((double)j - MARGIN_RANKS) * scale; if (lo_t < 0.0) lo_t = 0.0;
        double hi_t = ((double)j + MARGIN_RANKS) * scale;
        unsigned long long cum = 0;
        int lo = BINS1 - 1, hi = BINS1 - 1;
        bool fl = false, fh = false;
        for (int i = 0; i < 1024 && !fh; i++) {
            unsigned long long nc = cum + part[i];
            if ((!fl && (double)nc >= lo_t) || (!fh && (double)nc >= hi_t)) {
                unsigned long long c2 = cum;
                for (int k = 0; k < W; k++) {
                    c2 += g_hist1[m][i * W + k];
                    if (!fl && (double)c2 >= lo_t) { lo = i * W + k; fl = true; }
                    if (!fh && (double)c2 >= hi_t) { hi = i * W + k; fh = true; break; }
                }
            }
            cum = nc;
        }
        if (!fl) lo = BINS1 - 1;
        if (!fh) hi = BINS1 - 1;
        if (hi < lo) hi = lo;
        g_binLo[m] = lo;
        g_binHi[m] = hi;
    }
}

// ---------------------------------------------------------------------------
// The single full pass: write mask (tentative 0 for band), count below-band,
// gather in-band (bits, idx) with block-aggregated atomics.
__global__ void __launch_bounds__(1024) k_mask(const float* __restrict__ A,
                                               const float* __restrict__ B,
                                               float* __restrict__ out,
                                               int nA_i, int nB_i, long long nA) {
    int m = blockIdx.y;
    const float* srcf = m ? B : A;
    float* outf = out + (m ? nA : 0);
    int n = m ? nB_i : nA_i;
    int n4 = n >> 2;
    const float4* src4 = (const float4*)srcf;
    float4* out4 = (float4*)outf;
    const int lo = g_binLo[m];
    const int hi = g_binHi[m];

    __shared__ unsigned int sCnt;
    __shared__ unsigned int sBase;

    int t = blockIdx.x * blockDim.x + threadIdx.x;
    int T = gridDim.x * blockDim.x;
    int iters = (n4 + T - 1) / T;
    unsigned long long lless = 0;

    for (int it = 0; it < iters; it++) {
        int i4 = t + it * T;
        bool valid = (i4 < n4);
        if (threadIdx.x == 0) sCnt = 0u;
        __syncthreads();

        float r[4];
        unsigned int lb[4];
        unsigned int li[4];
        int lcnt = 0;
        if (valid) {
            float4 v = src4[i4];
            float vv[4] = {v.x, v.y, v.z, v.w};
#pragma unroll
            for (int c = 0; c < 4; c++) {
                unsigned int b = abs_bits(vv[c]);
                int bin = (int)(b >> SHIFT1);
                if (bin < lo) { r[c] = 0.0f; lless++; }
                else if (bin > hi) { r[c] = 1.0f; }
                else {
                    r[c] = 0.0f;
                    lb[lcnt] = b;
                    li[lcnt] = (unsigned int)(i4 * 4 + c);
                    lcnt++;
                }
            }
        }
        unsigned int myoff = 0;
        if (lcnt) myoff = atomicAdd(&sCnt, (unsigned int)lcnt);
        __syncthreads();
        if (threadIdx.x == 0) sBase = sCnt ? atomicAdd(&g_gcount[m], sCnt) : 0u;
        __syncthreads();
        if (lcnt) {
            unsigned int base = sBase + myoff;
            for (int k = 0; k < lcnt; k++) {
                unsigned int p = base + (unsigned int)k;
                if (p < GCAP) g_gather[m][p] = make_uint2(lb[k], li[k]);
            }
        }
        if (valid) out4[i4] = make_float4(r[0], r[1], r[2], r[3]);
    }

    // scalar tail (n % 4)
    int rem = n - n4 * 4;
    if (blockIdx.x == 0 && (int)threadIdx.x < rem) {
        int idx = n4 * 4 + (int)threadIdx.x;
        unsigned int b = abs_bits(srcf[idx]);
        int bin = (int)(b >> SHIFT1);
        float r;
        if (bin < lo) { r = 0.0f; lless++; }
        else if (bin > hi) { r = 1.0f; }
        else {
            r = 0.0f;
            unsigned int p = atomicAdd(&g_gcount[m], 1u);
            if (p < GCAP) g_gather[m][p] = make_uint2(b, (unsigned int)idx);
        }
        outf[idx] = r;
    }

    // reduce below-band count: warp reduce, then one atomic per warp
#pragma unroll
    for (int off = 16; off > 0; off >>= 1)
        lless += __shfl_down_sync(0xffffffffu, lless, off);
    if ((threadIdx.x & 31) == 0 && lless)
        atomicAdd(&g_count_less[m], lless);
}

// ---------------------------------------------------------------------------
__global__ void k_fhist1() {
    int m = blockIdx.y;
    unsigned int cnt = g_gcount[m]; if (cnt > GCAP) cnt = GCAP;
    unsigned int t = blockIdx.x * blockDim.x + threadIdx.x;
    unsigned int T = gridDim.x * blockDim.x;
    for (unsigned int i = t; i < cnt; i += T)
        atomicAdd(&g_fhist1[m][g_gather[m][i].x >> 16], 1u);
}

__global__ void __launch_bounds__(1024) k_scan1(long long nA, long long nB) {
    int m = blockIdx.x;
    long long n = m ? nB : nA;
    long long j = keep_j(n);
    __shared__ unsigned long long part[1024];
    int t = threadIdx.x;
    unsigned long long s = 0;
    for (int i = 0; i < FB / 1024; i++) s += g_fhist1[m][t * (FB / 1024) + i];
    part[t] = s;
    __syncthreads();
    if (t == 0) {
        long long need = j + 1 - (long long)g_count_less[m];
        if (need < 1) need = 1;  // degenerate guard
        unsigned long long cum = 0;
        int bucket = FB - 1;
        for (int i = 0; i < 1024; i++) {
            if ((long long)(cum + part[i]) >= need) {
                for (int k = 0; k < FB / 1024; k++) {
                    unsigned int h = g_fhist1[m][i * (FB / 1024) + k];
                    if ((long long)(cum + h) >= need) { bucket = i * (FB / 1024) + k; break; }
                    cum += h;
                }
                break;
            }
            cum += part[i];
        }
        g_bucket[m] = (unsigned int)bucket;
        g_rank_before[m] = g_count_less[m] + cum;  // # elems strictly below bucket
    }
}

__global__ void k_fhist2() {
    int m = blockIdx.y;
    unsigned int cnt = g_gcount[m]; if (cnt > GCAP) cnt = GCAP;
    unsigned int bkt = g_bucket[m];
    unsigned int t = blockIdx.x * blockDim.x + threadIdx.x;
    unsigned int T = gridDim.x * blockDim.x;
    for (unsigned int i = t; i < cnt; i += T) {
        uint2 e = g_gather[m][i];
        if ((e.x >> 16) == bkt) atomicAdd(&g_fhist2[m][e.x & 0xffffu], 1u);
    }
}

__global__ void __launch_bounds__(1024) k_scan2(long long nA, long long nB) {
    int m = blockIdx.x;
    long long n = m ? nB : nA;
    long long j = keep_j(n);
    __shared__ unsigned long long part[1024];
    int t = threadIdx.x;
    unsigned long long s = 0;
    for (int i = 0; i < FB / 1024; i++) s += g_fhist2[m][t * (FB / 1024) + i];
    part[t] = s;
    __syncthreads();
    if (t == 0) {
        long long need = j + 1 - (long long)g_rank_before[m];
        if (need < 1) need = 1;
        unsigned long long cum = 0;
        int L = FB - 1;
        for (int i = 0; i < 1024; i++) {
            if ((long long)(cum + part[i]) >= need) {
                for (int k = 0; k < FB / 1024; k++) {
                    unsigned int h = g_fhist2[m][i * (FB / 1024) + k];
                    if ((long long)(cum + h) >= need) { L = i * (FB / 1024) + k; break; }
                    cum += h;
                }
                break;
            }
            cum += part[i];
        }
        g_tbits[m] = (g_bucket[m] << 16) | (unsigned int)L;
        long long cntLess = (long long)g_rank_before[m] + (long long)cum;
        g_z[m] = j - cntLess;  // first z tied elems (by flat idx) stay 0
    }
}

// ---------------------------------------------------------------------------
// Scatter 1s for gathered entries strictly above threshold; collect exact ties.
__global__ void k_scatter(float* __restrict__ out, long long nA) {
    int m = blockIdx.y;
    float* outf = out + (m ? nA : 0);
    unsigned int cnt = g_gcount[m]; if (cnt > GCAP) cnt = GCAP;
    unsigned int tb = g_tbits[m];
    long long z = g_z[m];
    unsigned int t = blockIdx.x * blockDim.x + threadIdx.x;
    unsigned int T = gridDim.x * blockDim.x;
    for (unsigned int i = t; i < cnt; i += T) {
        uint2 e = g_gather[m][i];
        if (e.x > tb) {
            outf[e.y] = 1.0f;
        } else if (e.x == tb) {
            if (z == 0) {
                outf[e.y] = 1.0f;
            } else {
                unsigned int p = atomicAdd(&g_tiecnt[m], 1u);
                if (p < TIECAP) g_tie[m][p] = e.y;
            }
        }
    }
}

// Among tied elements, the z smallest flat indices stay 0; the rest -> 1.
__global__ void k_ties(float* __restrict__ out, long long nA) {
    int m = blockIdx.x;
    float* outf = out + (m ? nA : 0);
    unsigned int mt = g_tiecnt[m]; if (mt > TIECAP) mt = TIECAP;
    long long z = g_z[m];
    for (unsigned int i = threadIdx.x; i < mt; i += blockDim.x) {
        unsigned int my = g_tie[m][i];
        long long c = 0;
        for (unsigned int u = 0; u < mt; u++) c += (g_tie[m][u] < my) ? 1 : 0;
        if (c >= z) outf[my] = 1.0f;
    }
}

// ---------------------------------------------------------------------------
extern "C" void kernel_launch(void* const* d_in, const int* in_sizes, int n_in,
                              void* d_out, int out_size) {
    const float* A = (const float*)d_in[0];
    const float* B = (const float*)d_in[1];
    float* out = (float*)d_out;
    long long nA = in_sizes[0];
    long long nB = (n_in > 1) ? in_sizes[1] : 0;
    int n4A = (int)(nA >> 2);
    int n4B = (int)(nB >> 2);

    k_clear<<<256, 256>>>();

    dim3 gs(256, 2);
    k_sample<<<gs, 256>>>(A, B, n4A, n4B);

    k_band<<<2, 1024>>>(nA, nB);

    dim3 gm(592, 2);
    k_mask<<<gm, 1024>>>(A, B, out, (int)nA, (int)nB, nA);

    dim3 gf(148, 2);
    k_fhist1<<<gf, 256>>>();
    k_scan1<<<2, 1024>>>(nA, nB);
    k_fhist2<<<gf, 256>>>();
    k_scan2<<<2, 1024>>>(nA, nB);
    k_scatter<<<gf, 256>>>(out, nA);
    k_ties<<<2, 256>>>(out, nA);
}